// round 1
// baseline (speedup 1.0000x reference)
#include <cuda_runtime.h>
#include <cuda_bf16.h>

#define NB   512      // batch (docs)
#define NS   512      // seq len
#define NV   50265    // vocab
#define PAD  1

// Scratch (device globals only — no allocations allowed)
__device__ int   g_dl[NB];    // doc lengths (non-pad token counts)
__device__ float g_add[NB];   // k*(1 - b + b*dl/avgdl) per doc

// ---------------------------------------------------------------------------
// Kernel 1: per-row doc length (count of non-PAD tokens), coalesced reads.
// 512 blocks x 256 threads.
// ---------------------------------------------------------------------------
__global__ void k_doclen(const int* __restrict__ ids) {
    int b = blockIdx.x;
    int t = threadIdx.x;
    int cnt = 0;
    for (int j = t; j < NS; j += blockDim.x)
        cnt += (ids[b * NS + j] != PAD);

    // warp reduce
    #pragma unroll
    for (int o = 16; o; o >>= 1)
        cnt += __shfl_down_sync(0xffffffffu, cnt, o);

    __shared__ int red[8];
    if ((t & 31) == 0) red[t >> 5] = cnt;
    __syncthreads();
    if (t < 8) {
        int v = red[t];
        #pragma unroll
        for (int o = 4; o; o >>= 1)
            v += __shfl_down_sync(0xffu, v, o);
        if (t == 0) g_dl[b] = v;
    }
}

// ---------------------------------------------------------------------------
// Kernel 2: reduce doc lengths -> avgdl, precompute additive BM25 term.
// 1 block x 512 threads (one thread per doc).
// ---------------------------------------------------------------------------
__global__ void k_add() {
    const float Kp = 1.6f;
    const float Bp = 0.75f;

    int t  = threadIdx.x;
    int dl = g_dl[t];

    // block reduce sum of 512 ints
    int v = dl;
    #pragma unroll
    for (int o = 16; o; o >>= 1)
        v += __shfl_down_sync(0xffffffffu, v, o);

    __shared__ int   red[16];
    __shared__ float s_avg;
    if ((t & 31) == 0) red[t >> 5] = v;
    __syncthreads();
    if (t < 16) {
        int w = red[t];
        #pragma unroll
        for (int o = 8; o; o >>= 1)
            w += __shfl_down_sync(0xffffu, w, o);
        if (t == 0) s_avg = (float)w / (float)NB;   // avgdl
    }
    __syncthreads();

    float d_avg = (float)dl / s_avg;
    g_add[t] = Kp * (1.0f - Bp + Bp * d_avg);
}

// ---------------------------------------------------------------------------
// Kernel 3: per-row term-frequency + BM25 write.
// One block per doc, 512 threads (one per token position).
// Counts via brute-force O(S^2) with broadcast int4 shared loads.
// Output buffer already zeroed by memset; only nonzero entries are written.
// Duplicate tokens in a row write the identical value (benign).
// ---------------------------------------------------------------------------
__global__ void __launch_bounds__(512) k_main(const int* __restrict__ ids,
                                              float* __restrict__ out) {
    __shared__ __align__(16) int toks[NS];
    int b = blockIdx.x;
    int t = threadIdx.x;

    toks[t] = ids[b * NS + t];
    __syncthreads();

    int my  = toks[t];
    int cnt = 0;
    const int4* t4 = (const int4*)toks;
    #pragma unroll 8
    for (int j = 0; j < NS / 4; j++) {
        int4 q = t4[j];   // broadcast across the warp: conflict-free
        cnt += (q.x == my) + (q.y == my) + (q.z == my) + (q.w == my);
    }

    if (my != PAD) {
        float c   = (float)cnt;
        float val = c * 2.6f / (c + g_add[b]);   // k+1 = 2.6
        out[(size_t)b * NV + my] = val;
    }
}

// ---------------------------------------------------------------------------
extern "C" void kernel_launch(void* const* d_in, const int* in_sizes, int n_in,
                              void* d_out, int out_size) {
    const int* ids = (const int*)d_in[0];
    float*     out = (float*)d_out;

    // Zero-fill the whole 103 MB output (driver-optimized, graph-capturable).
    cudaMemsetAsync(d_out, 0, (size_t)out_size * sizeof(float), 0);

    k_doclen<<<NB, 256>>>(ids);
    k_add<<<1, NB>>>();
    k_main<<<NB, 512>>>(ids, out);
}

// round 3
// speedup vs baseline: 1.1632x; 1.1632x over previous
#include <cuda_runtime.h>
#include <cuda_bf16.h>
#include <stdint.h>

#define NB   512      // batch (docs)
#define NS   512      // seq len
#define NV   50265    // vocab
#define PAD  1

// Scratch (device globals only — no allocations allowed)
__device__ int g_dl[NB];    // doc lengths (non-pad token counts)
__device__ int g_dlsum;     // grid-wide sum of doc lengths

// ---------------------------------------------------------------------------
// Kernel 0: reset the global accumulator (deterministic across graph replays).
// ---------------------------------------------------------------------------
__global__ void k_zero() { g_dlsum = 0; }

// ---------------------------------------------------------------------------
// Kernel 1: per-row doc length. 512 blocks x 128 threads, one int4 per thread.
// Also accumulates the grid total via one red.global per block.
// ---------------------------------------------------------------------------
__global__ void __launch_bounds__(128) k_doclen(const int* __restrict__ ids) {
    int b = blockIdx.x;
    int t = threadIdx.x;
    const int4* row4 = (const int4*)(ids + b * NS);
    int4 q = row4[t];                      // 128 threads x int4 = 512 ints
    int cnt = (q.x != PAD) + (q.y != PAD) + (q.z != PAD) + (q.w != PAD);

    #pragma unroll
    for (int o = 16; o; o >>= 1)
        cnt += __shfl_down_sync(0xffffffffu, cnt, o);

    __shared__ int red[4];
    if ((t & 31) == 0) red[t >> 5] = cnt;
    __syncthreads();
    if (t == 0) {
        int s = red[0] + red[1] + red[2] + red[3];
        g_dl[b] = s;
        atomicAdd(&g_dlsum, s);           // REDG, no return
    }
}

// ---------------------------------------------------------------------------
// Kernel 2 (fused): zero-fill row + BM25 TF count + scatter.
// One block per doc, 512 threads. The zero-fill stores (201 KB/row) are the
// DRAM-bound term; the LDS-broadcast count loop hides underneath them.
// ---------------------------------------------------------------------------
__global__ void __launch_bounds__(512) k_main(const int* __restrict__ ids,
                                              float* __restrict__ out) {
    __shared__ __align__(16) int toks[NS];
    __shared__ float s_add;

    int b = blockIdx.x;
    int t = threadIdx.x;

    // Stage this row's tokens in shared.
    toks[t] = ids[b * NS + t];

    // Per-row BM25 additive term (two scalar L2 loads, one thread).
    if (t == 0) {
        float avgdl = (float)g_dlsum / (float)NB;
        float d_avg = (float)g_dl[b] / avgdl;
        s_add = 1.6f * (1.0f - 0.75f + 0.75f * d_avg);   // k*(1-b+b*d_avg)
    }

    // --- Zero-fill this row with wide stores (independent of the above). ---
    float* row = out + (size_t)b * NV;
    // (b*NV) % 4 == b % 4  (since NV % 4 == 1): rotating 16B alignment.
    int head = (4 - (b & 3)) & 3;
    if (t < head) row[t] = 0.0f;
    float4* r4  = (float4*)(row + head);
    int nvec    = (NV - head) >> 2;                   // # of float4 in body
    const float4 z4 = make_float4(0.f, 0.f, 0.f, 0.f);
    for (int i = t; i < nvec; i += 512)
        r4[i] = z4;
    for (int i = head + (nvec << 2) + t; i < NV; i += 512)
        row[i] = 0.0f;

    __syncthreads();   // publishes toks[], s_add; orders zero stores before scatter

    // --- Term frequency: O(S^2) via broadcast LDS.128 (conflict-free). ---
    int my  = toks[t];
    int cnt = 0;
    const int4* t4 = (const int4*)toks;
    #pragma unroll 8
    for (int j = 0; j < NS / 4; j++) {
        int4 q = t4[j];
        cnt += (q.x == my) + (q.y == my) + (q.z == my) + (q.w == my);
    }

    // --- Scatter BM25 value (overwrites zero; dup tokens write same val). ---
    if (my != PAD) {
        float c = (float)cnt;
        row[my] = c * 2.6f / (c + s_add);    // (k+1) = 2.6
    }
}

// ---------------------------------------------------------------------------
extern "C" void kernel_launch(void* const* d_in, const int* in_sizes, int n_in,
                              void* d_out, int out_size) {
    const int* ids = (const int*)d_in[0];
    float*     out = (float*)d_out;

    k_zero<<<1, 1>>>();
    k_doclen<<<NB, 128>>>(ids);
    k_main<<<NB, 512>>>(ids, out);
}